// round 8
// baseline (speedup 1.0000x reference)
#include <cuda_runtime.h>

typedef unsigned long long u64;
struct uu2 { u64 a, b; };

// ---------------- merged weight blob (one constant upload) ----------------
// lin:  [r*24+o] splatted Wl pairs (r = t2*16+ch, feature f = ch*6+t2), then 24 splatted bl
// pack: [0..192) w12p[(ci*3+k)*8+co] | [192..576) w21p[(ci*3+k)*16+co]
//       [576..1344) w22p[(ci*3+k)*16+co] | [1344..3648) unused
//       [3648..3672) w11p[k*8+co] | [3672..3680) b11 | [3680..3688) b12
//       [3688..3704) b21 | [3704..3720) b22 | [3720..3744) bl
#define LINW (96 * 24)
#define PACKN 3744
struct __align__(16) AllW {
    u64   lin[LINW + 24];
    float pack[PACKN];
};
__device__ AllW g_all;
__constant__ AllW c_all;

// global scratch: p1 [8*12 features][sample], p2 [96 features][sample]
#define MAXN 131072
__device__ float g_p1[96 * MAXN];
__device__ float g_p2[96 * MAXN];

__device__ __forceinline__ u64 pk2(float lo, float hi) {
    u64 r; asm("mov.b64 %0,{%1,%2};" : "=l"(r) : "f"(lo), "f"(hi)); return r;
}
__device__ __forceinline__ float2 upk2(u64 v) {
    float2 f; asm("mov.b64 {%0,%1},%2;" : "=f"(f.x), "=f"(f.y) : "l"(v)); return f;
}
__device__ __forceinline__ u64 ffma2(u64 a, u64 b, u64 c) {
    u64 d; asm("fma.rn.f32x2 %0,%1,%2,%3;" : "=l"(d) : "l"(a), "l"(b), "l"(c)); return d;
}
__device__ __forceinline__ uu2 cpk4(int idx) {          // LDC.128 (idx multiple of 4)
    ulonglong2 v = *reinterpret_cast<const ulonglong2*>(&c_all.pack[idx]);
    uu2 r; r.a = v.x; r.b = v.y; return r;
}

__global__ void repack_kernel(
    const float* __restrict__ w11, const float* __restrict__ b11,
    const float* __restrict__ w12, const float* __restrict__ b12,
    const float* __restrict__ w21, const float* __restrict__ b21,
    const float* __restrict__ w22, const float* __restrict__ b22,
    const float* __restrict__ Wl,  const float* __restrict__ bl)
{
    int gtid = blockIdx.x * 256 + threadIdx.x;
    int stride = gridDim.x * 256;
    for (int i = gtid; i < 192;  i += stride) g_all.pack[i]       = w12[(i & 7)  * 24 + (i >> 3)];
    for (int i = gtid; i < 384;  i += stride) g_all.pack[192 + i] = w21[(i & 15) * 24 + (i >> 4)];
    for (int i = gtid; i < 768;  i += stride) g_all.pack[576 + i] = w22[(i & 15) * 48 + (i >> 4)];
    for (int i = gtid; i < 2304; i += stride) {
        int o = i % 24; int r = i / 24;
        float w = Wl[o * 96 + (r & 15) * 6 + (r >> 4)];
        g_all.lin[i] = pk2(w, w);
    }
    if (gtid < 24) g_all.lin[LINW + gtid] = pk2(bl[gtid], bl[gtid]);
    if (gtid < 24) g_all.pack[3648 + gtid] = w11[(gtid & 7) * 3 + (gtid >> 3)];
    if (gtid < 8)  g_all.pack[3672 + gtid] = b11[gtid];
    if (gtid < 8)  g_all.pack[3680 + gtid] = b12[gtid];
    if (gtid < 16) g_all.pack[3688 + gtid] = b21[gtid];
    if (gtid < 16) g_all.pack[3704 + gtid] = b22[gtid];
    if (gtid < 24) g_all.pack[3720 + gtid] = bl[gtid];
}

// ================= stage A: conv11 -> relu -> conv12 -> relu -> pool -> p1 (global) =========
__global__ void __launch_bounds__(128, 5)
stageA(const float* __restrict__ x, int n)
{
    int s = blockIdx.x * 128 + threadIdx.x;
    if (s >= n) return;

    float xv[24];
    {
        const float4* xg = reinterpret_cast<const float4*>(x + (size_t)s * 24);
#pragma unroll
        for (int i = 0; i < 6; i++) {
            float4 v = xg[i];
            xv[4*i] = v.x; xv[4*i+1] = v.y; xv[4*i+2] = v.z; xv[4*i+3] = v.w;
        }
    }

    float h1[4][8];
    auto H1 = [&](int pos) {
        float xm = (pos > 0)  ? xv[pos - 1] : 0.f;
        float xc = xv[pos];
        float xp = (pos < 23) ? xv[pos + 1] : 0.f;
        float* d = h1[pos & 3];
#pragma unroll
        for (int c = 0; c < 8; c++)
            d[c] = fmaxf(fmaf(c_all.pack[3648 + 16 + c], xp,
                         fmaf(c_all.pack[3648 + 8 + c],  xc,
                         fmaf(c_all.pack[3648 + c],      xm, c_all.pack[3672 + c]))), 0.f);
    };
    H1(0); H1(1); H1(2);

#pragma unroll
    for (int t = 0; t < 12; t++) {
        u64 Ae[4], Ao[4];
        {
            uu2 b01 = cpk4(3680), b23 = cpk4(3684);
            Ae[0] = b01.a; Ae[1] = b01.b; Ae[2] = b23.a; Ae[3] = b23.b;
            Ao[0] = b01.a; Ao[1] = b01.b; Ao[2] = b23.a; Ao[3] = b23.b;
        }
#pragma unroll
        for (int ci = 0; ci < 8; ci++) {
#pragma unroll
            for (int k = 0; k < 3; k++) {
                int pe = 2*t + k - 1, po = 2*t + k;
                u64 se = (pe < 0)  ? 0ull : pk2(h1[pe & 3][ci], h1[pe & 3][ci]);
                u64 so = (po > 23) ? 0ull : pk2(h1[po & 3][ci], h1[po & 3][ci]);
                uu2 w01 = cpk4((ci*3 + k) * 8);
                uu2 w23 = cpk4((ci*3 + k) * 8 + 4);
                Ae[0] = ffma2(w01.a, se, Ae[0]);  Ao[0] = ffma2(w01.a, so, Ao[0]);
                Ae[1] = ffma2(w01.b, se, Ae[1]);  Ao[1] = ffma2(w01.b, so, Ao[1]);
                Ae[2] = ffma2(w23.a, se, Ae[2]);  Ao[2] = ffma2(w23.a, so, Ao[2]);
                Ae[3] = ffma2(w23.b, se, Ae[3]);  Ao[3] = ffma2(w23.b, so, Ao[3]);
            }
        }
#pragma unroll
        for (int p = 0; p < 4; p++) {
            float2 e = upk2(Ae[p]), o = upk2(Ao[p]);
            g_p1[(size_t)((2*p)     * 12 + t) * n + s] = fmaxf(fmaxf(e.x, o.x), 0.f);
            g_p1[(size_t)((2*p + 1) * 12 + t) * n + s] = fmaxf(fmaxf(e.y, o.y), 0.f);
        }
        if (t < 11) H1(2*t + 3);
        if (t < 10) H1(2*t + 4);
    }
}

// ================= stage B: conv21 -> relu -> conv22 -> relu -> pool -> p2 (global) =========
__global__ void __launch_bounds__(128, 4)
stageB(int n)
{
    int s = blockIdx.x * 128 + threadIdx.x;
    if (s >= n) return;

    float r3[3][16];                            // h3 ring, 3 positions
    auto H3 = [&](int j) {
        u64 D[8];
#pragma unroll
        for (int h = 0; h < 4; h++) {
            uu2 b = cpk4(3688 + 4*h);
            D[2*h] = b.a; D[2*h + 1] = b.b;
        }
#pragma unroll
        for (int ci = 0; ci < 8; ci++) {
#pragma unroll
            for (int k = 0; k < 3; k++) {
                int col = j + k - 1;
                if (col >= 0 && col <= 11) {
                    float g = g_p1[(size_t)(ci * 12 + col) * n + s];
                    u64 sg = pk2(g, g);
                    int wb = 192 + (ci*3 + k) * 16;
#pragma unroll
                    for (int h = 0; h < 4; h++) {
                        uu2 w = cpk4(wb + 4*h);
                        D[2*h]     = ffma2(w.a, sg, D[2*h]);
                        D[2*h + 1] = ffma2(w.b, sg, D[2*h + 1]);
                    }
                }
            }
        }
        float* o = r3[j % 3];
#pragma unroll
        for (int p = 0; p < 8; p++) {
            float2 v = upk2(D[p]);
            o[2*p] = fmaxf(v.x, 0.f); o[2*p + 1] = fmaxf(v.y, 0.f);
        }
    };

    auto C22 = [&](int pos, u64 A[8]) {         // accumulate conv22(pos) into A (no relu)
#pragma unroll
        for (int h = 0; h < 4; h++) {
            uu2 b = cpk4(3704 + 4*h);
            A[2*h] = b.a; A[2*h + 1] = b.b;
        }
#pragma unroll
        for (int ci = 0; ci < 16; ci++) {
#pragma unroll
            for (int k = 0; k < 3; k++) {
                int col = pos + k - 1;
                if (col >= 0 && col <= 11) {
                    float g = r3[col % 3][ci];
                    u64 sg = pk2(g, g);
                    int wb = 576 + (ci*3 + k) * 16;
#pragma unroll
                    for (int h = 0; h < 4; h++) {
                        uu2 w = cpk4(wb + 4*h);
                        A[2*h]     = ffma2(w.a, sg, A[2*h]);
                        A[2*h + 1] = ffma2(w.b, sg, A[2*h + 1]);
                    }
                }
            }
        }
    };

    H3(0); H3(1);
#pragma unroll
    for (int t2 = 0; t2 < 6; t2++) {
        u64 AA[8], AB[8];
        C22(2*t2, AA);                          // needs h3(2t2-1..2t2+1)
        if (2*t2 + 2 <= 11) H3(2*t2 + 2);
        C22(2*t2 + 1, AB);                      // needs h3(2t2..2t2+2)
#pragma unroll
        for (int p = 0; p < 8; p++) {
            float2 a = upk2(AA[p]), b = upk2(AB[p]);
            g_p2[(size_t)(t2 * 16 + 2*p)     * n + s] = fmaxf(fmaxf(a.x, b.x), 0.f);
            g_p2[(size_t)(t2 * 16 + 2*p + 1) * n + s] = fmaxf(fmaxf(a.y, b.y), 0.f);
        }
        if (2*t2 + 3 <= 11) H3(2*t2 + 3);
    }
}

// ================= linear: out = p2 @ Wl^T + bl, 4 samples/thread, f32x2 sample packing =====
__global__ void __launch_bounds__(128)
lin_kernel(float* __restrict__ out, int n)
{
    int i = blockIdx.x * 128 + threadIdx.x;
    int s0 = 4 * i;
    if (s0 >= n) return;

    if (s0 + 3 < n) {
        u64 aA[24], aB[24];
#pragma unroll
        for (int o = 0; o < 24; o++) { u64 b = c_all.lin[LINW + o]; aA[o] = b; aB[o] = b; }
#pragma unroll 8
        for (int r = 0; r < 96; r++) {
            float4 v = *reinterpret_cast<const float4*>(&g_p2[(size_t)r * n + s0]);
            u64 pA = pk2(v.x, v.y), pB = pk2(v.z, v.w);
            const u64* w = &c_all.lin[r * 24];
#pragma unroll
            for (int h = 0; h < 12; h++) {
                ulonglong2 w2 = *reinterpret_cast<const ulonglong2*>(&w[2*h]);
                aA[2*h]     = ffma2(w2.x, pA, aA[2*h]);
                aA[2*h + 1] = ffma2(w2.y, pA, aA[2*h + 1]);
                aB[2*h]     = ffma2(w2.x, pB, aB[2*h]);
                aB[2*h + 1] = ffma2(w2.y, pB, aB[2*h + 1]);
            }
        }
        float r0[24], r1[24], r2[24], r3[24];
#pragma unroll
        for (int o = 0; o < 24; o++) {
            float2 a = upk2(aA[o]), b = upk2(aB[o]);
            r0[o] = a.x; r1[o] = a.y; r2[o] = b.x; r3[o] = b.y;
        }
        float4* o0 = reinterpret_cast<float4*>(out + (size_t)s0 * 24);
        float4* o1 = reinterpret_cast<float4*>(out + (size_t)(s0 + 1) * 24);
        float4* o2 = reinterpret_cast<float4*>(out + (size_t)(s0 + 2) * 24);
        float4* o3 = reinterpret_cast<float4*>(out + (size_t)(s0 + 3) * 24);
#pragma unroll
        for (int q = 0; q < 6; q++) {
            o0[q] = make_float4(r0[4*q], r0[4*q+1], r0[4*q+2], r0[4*q+3]);
            o1[q] = make_float4(r1[4*q], r1[4*q+1], r1[4*q+2], r1[4*q+3]);
            o2[q] = make_float4(r2[4*q], r2[4*q+1], r2[4*q+2], r2[4*q+3]);
            o3[q] = make_float4(r3[4*q], r3[4*q+1], r3[4*q+2], r3[4*q+3]);
        }
    } else {
        for (int s = s0; s < n; s++) {
            float acc[24];
#pragma unroll
            for (int o = 0; o < 24; o++) acc[o] = upk2(c_all.lin[LINW + o]).x;
            for (int r = 0; r < 96; r++) {
                float v = g_p2[(size_t)r * n + s];
#pragma unroll
                for (int o = 0; o < 24; o++)
                    acc[o] = fmaf(upk2(c_all.lin[r*24 + o]).x, v, acc[o]);
            }
#pragma unroll
            for (int o = 0; o < 24; o++) out[(size_t)s * 24 + o] = acc[o];
        }
    }
}

extern "C" void kernel_launch(void* const* d_in, const int* in_sizes, int n_in,
                              void* d_out, int out_size)
{
    const float* x = (const float*)d_in[0];

    repack_kernel<<<10, 256>>>(
        (const float*)d_in[1], (const float*)d_in[2],
        (const float*)d_in[3], (const float*)d_in[4],
        (const float*)d_in[5], (const float*)d_in[6],
        (const float*)d_in[7], (const float*)d_in[8],
        (const float*)d_in[9], (const float*)d_in[10]);

    void *ca, *ga;
    cudaGetSymbolAddress(&ca, c_all);
    cudaGetSymbolAddress(&ga, g_all);
    cudaMemcpyAsync(ca, ga, sizeof(AllW), cudaMemcpyDeviceToDevice, 0);

    int nSamples = in_sizes[0] / 24;            // 512*256 = 131072 (<= MAXN)
    int blocks = (nSamples + 127) / 128;
    stageA<<<blocks, 128>>>(x, nSamples);
    stageB<<<blocks, 128>>>(nSamples);

    int lblocks = ((nSamples + 3) / 4 + 127) / 128;
    lin_kernel<<<lblocks, 128>>>((float*)d_out, nSamples);
}

// round 9
// speedup vs baseline: 1.1289x; 1.1289x over previous
#include <cuda_runtime.h>

typedef unsigned long long u64;
struct uu2 { u64 a, b; };

// ---------------- packed weights (consumption order, one constant blob) ----------------
//   [0    ..192 )  w12p[(ci*3+k)*8  + co]
//   [192  ..576 )  w21p[(ci*3+k)*16 + co]
//   [576  ..1344)  w22p[(ci*3+k)*16 + co]
//   [1344 ..3648)  Wlp [(t2*16+ch)*24 + o]   (feature r = t2*16+ch maps to f = ch*6+t2)
//   [3648 ..3672)  w11p[k*8 + co]
//   [3672 ..3680)  b11  [3680..3688) b12  [3688..3704) b21
//   [3704 ..3720)  b22  [3720..3744) bl
#define PACKN 3744
__device__ __align__(16) float g_pack[PACKN];
__constant__ __align__(16) float c_pack[PACKN];

// p2 scratch [feature r][sample]
#define MAXN 131072
__device__ float g_p2[96 * MAXN];

__device__ __forceinline__ u64 pk2(float lo, float hi) {
    u64 r; asm("mov.b64 %0,{%1,%2};" : "=l"(r) : "f"(lo), "f"(hi)); return r;
}
__device__ __forceinline__ float2 upk2(u64 v) {
    float2 f; asm("mov.b64 {%0,%1},%2;" : "=f"(f.x), "=f"(f.y) : "l"(v)); return f;
}
__device__ __forceinline__ u64 ffma2(u64 a, u64 b, u64 c) {
    u64 d; asm("fma.rn.f32x2 %0,%1,%2,%3;" : "=l"(d) : "l"(a), "l"(b), "l"(c)); return d;
}
__device__ __forceinline__ uu2 cpk4(int idx) {          // LDC.128 (idx multiple of 4)
    ulonglong2 v = *reinterpret_cast<const ulonglong2*>(&c_pack[idx]);
    uu2 r; r.a = v.x; r.b = v.y; return r;
}

__global__ void repack_kernel(
    const float* __restrict__ w11, const float* __restrict__ b11,
    const float* __restrict__ w12, const float* __restrict__ b12,
    const float* __restrict__ w21, const float* __restrict__ b21,
    const float* __restrict__ w22, const float* __restrict__ b22,
    const float* __restrict__ Wl,  const float* __restrict__ bl)
{
    int gtid = blockIdx.x * 256 + threadIdx.x;
    int stride = gridDim.x * 256;
    for (int i = gtid; i < 192;  i += stride) g_pack[i]       = w12[(i & 7)  * 24 + (i >> 3)];
    for (int i = gtid; i < 384;  i += stride) g_pack[192 + i] = w21[(i & 15) * 24 + (i >> 4)];
    for (int i = gtid; i < 768;  i += stride) g_pack[576 + i] = w22[(i & 15) * 48 + (i >> 4)];
    for (int i = gtid; i < 2304; i += stride) {
        int o = i % 24; int r = i / 24;
        g_pack[1344 + i] = Wl[o * 96 + (r & 15) * 6 + (r >> 4)];
    }
    if (gtid < 24) g_pack[3648 + gtid] = w11[(gtid & 7) * 3 + (gtid >> 3)];
    if (gtid < 8)  g_pack[3672 + gtid] = b11[gtid];
    if (gtid < 8)  g_pack[3680 + gtid] = b12[gtid];
    if (gtid < 16) g_pack[3688 + gtid] = b21[gtid];
    if (gtid < 16) g_pack[3704 + gtid] = b22[gtid];
    if (gtid < 24) g_pack[3720 + gtid] = bl[gtid];
}

// per-thread p1 scratch in dynamic smem: p1[(ci*12+col)*128 + tid]
#define P1_STRIDE 128
#define SMEM_BYTES (96 * 128 * 4)

__global__ void __launch_bounds__(128, 4)
cnn_main(const float* __restrict__ x, int n)
{
    extern __shared__ float p1s_base[];
    float* p1s = p1s_base + threadIdx.x;

    int s = blockIdx.x * 128 + threadIdx.x;
    if (s >= n) return;

    // ---- input sample ----
    float xv[24];
    {
        const float4* xg = reinterpret_cast<const float4*>(x + (size_t)s * 24);
#pragma unroll
        for (int i = 0; i < 6; i++) {
            float4 v = xg[i];
            xv[4*i] = v.x; xv[4*i+1] = v.y; xv[4*i+2] = v.z; xv[4*i+3] = v.w;
        }
    }

    // ============ stage A: conv11 -> relu -> conv12 -> relu -> pool -> p1 (smem) ============
    float h1[4][8];
    auto H1 = [&](int pos) {
        float xm = (pos > 0)  ? xv[pos - 1] : 0.f;
        float xc = xv[pos];
        float xp = (pos < 23) ? xv[pos + 1] : 0.f;
        float* d = h1[pos & 3];
#pragma unroll
        for (int c = 0; c < 8; c++)
            d[c] = fmaxf(fmaf(c_pack[3648 + 16 + c], xp,
                         fmaf(c_pack[3648 + 8 + c],  xc,
                         fmaf(c_pack[3648 + c],      xm, c_pack[3672 + c]))), 0.f);
    };
    H1(0); H1(1); H1(2);

#pragma unroll
    for (int t = 0; t < 12; t++) {
        u64 Ae[4], Ao[4];
        {
            uu2 b01 = cpk4(3680), b23 = cpk4(3684);
            Ae[0] = b01.a; Ae[1] = b01.b; Ae[2] = b23.a; Ae[3] = b23.b;
            Ao[0] = b01.a; Ao[1] = b01.b; Ao[2] = b23.a; Ao[3] = b23.b;
        }
#pragma unroll
        for (int ci = 0; ci < 8; ci++) {
#pragma unroll
            for (int k = 0; k < 3; k++) {
                int pe = 2*t + k - 1, po = 2*t + k;
                u64 se = (pe < 0)  ? 0ull : pk2(h1[pe & 3][ci], h1[pe & 3][ci]);
                u64 so = (po > 23) ? 0ull : pk2(h1[po & 3][ci], h1[po & 3][ci]);
                uu2 w01 = cpk4((ci*3 + k) * 8);
                uu2 w23 = cpk4((ci*3 + k) * 8 + 4);
                Ae[0] = ffma2(w01.a, se, Ae[0]);  Ao[0] = ffma2(w01.a, so, Ao[0]);
                Ae[1] = ffma2(w01.b, se, Ae[1]);  Ao[1] = ffma2(w01.b, so, Ao[1]);
                Ae[2] = ffma2(w23.a, se, Ae[2]);  Ao[2] = ffma2(w23.a, so, Ao[2]);
                Ae[3] = ffma2(w23.b, se, Ae[3]);  Ao[3] = ffma2(w23.b, so, Ao[3]);
            }
        }
#pragma unroll
        for (int p = 0; p < 4; p++) {
            float2 e = upk2(Ae[p]), o = upk2(Ao[p]);
            p1s[((2*p)     * 12 + t) * P1_STRIDE] = fmaxf(fmaxf(e.x, o.x), 0.f);
            p1s[((2*p + 1) * 12 + t) * P1_STRIDE] = fmaxf(fmaxf(e.y, o.y), 0.f);
        }
        if (t < 11) H1(2*t + 3);
        if (t < 10) H1(2*t + 4);
    }

    // ============ stage B: conv21 -> relu -> conv22 -> relu -> pool -> p2 (global) ============
    float r3[3][16];
    auto H3 = [&](int j) {
        u64 D[8];
#pragma unroll
        for (int h = 0; h < 4; h++) {
            uu2 b = cpk4(3688 + 4*h);
            D[2*h] = b.a; D[2*h + 1] = b.b;
        }
#pragma unroll
        for (int ci = 0; ci < 8; ci++) {
#pragma unroll
            for (int k = 0; k < 3; k++) {
                int col = j + k - 1;
                if (col >= 0 && col <= 11) {
                    float g = p1s[(ci * 12 + col) * P1_STRIDE];
                    u64 sg = pk2(g, g);
                    int wb = 192 + (ci*3 + k) * 16;
#pragma unroll
                    for (int h = 0; h < 4; h++) {
                        uu2 w = cpk4(wb + 4*h);
                        D[2*h]     = ffma2(w.a, sg, D[2*h]);
                        D[2*h + 1] = ffma2(w.b, sg, D[2*h + 1]);
                    }
                }
            }
        }
        float* o = r3[j % 3];
#pragma unroll
        for (int p = 0; p < 8; p++) {
            float2 v = upk2(D[p]);
            o[2*p] = fmaxf(v.x, 0.f); o[2*p + 1] = fmaxf(v.y, 0.f);
        }
    };

    auto C22 = [&](int pos, u64 A[8]) {
#pragma unroll
        for (int h = 0; h < 4; h++) {
            uu2 b = cpk4(3704 + 4*h);
            A[2*h] = b.a; A[2*h + 1] = b.b;
        }
#pragma unroll
        for (int ci = 0; ci < 16; ci++) {
#pragma unroll
            for (int k = 0; k < 3; k++) {
                int col = pos + k - 1;
                if (col >= 0 && col <= 11) {
                    float g = r3[col % 3][ci];
                    u64 sg = pk2(g, g);
                    int wb = 576 + (ci*3 + k) * 16;
#pragma unroll
                    for (int h = 0; h < 4; h++) {
                        uu2 w = cpk4(wb + 4*h);
                        A[2*h]     = ffma2(w.a, sg, A[2*h]);
                        A[2*h + 1] = ffma2(w.b, sg, A[2*h + 1]);
                    }
                }
            }
        }
    };

    H3(0); H3(1);
#pragma unroll
    for (int t2 = 0; t2 < 6; t2++) {
        u64 AA[8], AB[8];
        C22(2*t2, AA);
        if (2*t2 + 2 <= 11) H3(2*t2 + 2);
        C22(2*t2 + 1, AB);
#pragma unroll
        for (int p = 0; p < 8; p++) {
            float2 a = upk2(AA[p]), b = upk2(AB[p]);
            g_p2[(size_t)(t2 * 16 + 2*p)     * n + s] = fmaxf(fmaxf(a.x, b.x), 0.f);
            g_p2[(size_t)(t2 * 16 + 2*p + 1) * n + s] = fmaxf(fmaxf(a.y, b.y), 0.f);
        }
        if (2*t2 + 3 <= 11) H3(2*t2 + 3);
    }
}

// ============ linear: out = p2 @ Wl^T + bl ; 1 sample/thread, channel-pair packing ==========
__global__ void __launch_bounds__(128)
lin_kernel(float* __restrict__ out, int n)
{
    int s = blockIdx.x * 128 + threadIdx.x;
    if (s >= n) return;

    u64 acc2[12];
#pragma unroll
    for (int h = 0; h < 6; h++) {
        uu2 b = cpk4(3720 + 4*h);
        acc2[2*h] = b.a; acc2[2*h + 1] = b.b;
    }
#pragma unroll 8
    for (int r = 0; r < 96; r++) {
        float v = g_p2[(size_t)r * n + s];
        u64 sv = pk2(v, v);
        int wb = 1344 + r * 24;
#pragma unroll
        for (int h = 0; h < 6; h++) {
            uu2 w = cpk4(wb + 4*h);
            acc2[2*h]     = ffma2(w.a, sv, acc2[2*h]);
            acc2[2*h + 1] = ffma2(w.b, sv, acc2[2*h + 1]);
        }
    }

    float res[24];
#pragma unroll
    for (int q = 0; q < 12; q++) {
        float2 v = upk2(acc2[q]);
        res[2*q] = v.x; res[2*q + 1] = v.y;
    }
    float4* og = reinterpret_cast<float4*>(out + (size_t)s * 24);
#pragma unroll
    for (int i = 0; i < 6; i++)
        og[i] = make_float4(res[4*i], res[4*i+1], res[4*i+2], res[4*i+3]);
}

extern "C" void kernel_launch(void* const* d_in, const int* in_sizes, int n_in,
                              void* d_out, int out_size)
{
    const float* x = (const float*)d_in[0];

    repack_kernel<<<10, 256>>>(
        (const float*)d_in[1], (const float*)d_in[2],
        (const float*)d_in[3], (const float*)d_in[4],
        (const float*)d_in[5], (const float*)d_in[6],
        (const float*)d_in[7], (const float*)d_in[8],
        (const float*)d_in[9], (const float*)d_in[10]);

    void *cp, *gp;
    cudaGetSymbolAddress(&cp, c_pack);
    cudaGetSymbolAddress(&gp, g_pack);
    cudaMemcpyAsync(cp, gp, PACKN * sizeof(float), cudaMemcpyDeviceToDevice, 0);

    static bool attr_set = false;
    if (!attr_set) {
        cudaFuncSetAttribute(cnn_main,
                             cudaFuncAttributeMaxDynamicSharedMemorySize, SMEM_BYTES);
        attr_set = true;
    }

    int nSamples = in_sizes[0] / 24;            // 512*256 = 131072 (<= MAXN)
    int blocks = (nSamples + 127) / 128;
    cnn_main<<<blocks, 128, SMEM_BYTES>>>(x, nSamples);
    lin_kernel<<<blocks, 128>>>((float*)d_out, nSamples);
}